// round 6
// baseline (speedup 1.0000x reference)
#include <cuda_runtime.h>
#include <cuda_fp16.h>
#include <cstdint>

// ---------------- problem dims ----------------
#define B_SZ 16384
#define D_SZ 512
#define O_SZ 512
#define KTOT 4608               // 512 silu + 4096 basis (i-major groups of 8)

// ---------------- GEMM tiling ----------------
#define BM 128
#define BN 128
#define BK 64                   // 64 fp16 = 128 bytes = one swizzled row
#define STAGES 3
#define NKIT (KTOT / BK)        // 72
#define NTHREADS 128            // 4 warps, warp tile 64x64

#define SA_STAGE (BM * BK * 2)              // 16 KB
#define SB_STAGE (BN * BK * 2)              // 16 KB
#define STAGE_BYTES (SA_STAGE + SB_STAGE)
#define SMEM_BYTES (STAGES * STAGE_BYTES)   // 96 KB  (x2 CTAs = 192 KB/SM)

// ---------------- scratch (device globals; no allocation allowed) ----------------
__device__ __half g_A[(size_t)B_SZ * KTOT];   // ~151 MB
__device__ __half g_W[(size_t)O_SZ * KTOT];   // ~4.7 MB

// ---------------- helpers ----------------
__device__ __forceinline__ uint32_t smem_u32(const void* p) {
    return (uint32_t)__cvta_generic_to_shared(p);
}
__device__ __forceinline__ void cp_async16(uint32_t saddr, const void* g) {
    asm volatile("cp.async.cg.shared.global [%0], [%1], 16;" :: "r"(saddr), "l"(g) : "memory");
}
__device__ __forceinline__ void cp_commit() {
    asm volatile("cp.async.commit_group;" ::: "memory");
}
template <int N> __device__ __forceinline__ void cp_wait() {
    asm volatile("cp.async.wait_group %0;" :: "n"(N) : "memory");
}
__device__ __forceinline__ void ldsm_x4(uint32_t& r0, uint32_t& r1, uint32_t& r2, uint32_t& r3,
                                        uint32_t addr) {
    asm volatile("ldmatrix.sync.aligned.m8n8.x4.shared.b16 {%0,%1,%2,%3}, [%4];"
                 : "=r"(r0), "=r"(r1), "=r"(r2), "=r"(r3) : "r"(addr));
}
__device__ __forceinline__ void mma16816(float& c0, float& c1, float& c2, float& c3,
                                         uint32_t a0, uint32_t a1, uint32_t a2, uint32_t a3,
                                         uint32_t b0, uint32_t b1) {
    asm volatile(
        "mma.sync.aligned.m16n8k16.row.col.f32.f16.f16.f32 "
        "{%0,%1,%2,%3}, {%4,%5,%6,%7}, {%8,%9}, {%0,%1,%2,%3};"
        : "+f"(c0), "+f"(c1), "+f"(c2), "+f"(c3)
        : "r"(a0), "r"(a1), "r"(a2), "r"(a3), "r"(b0), "r"(b1));
}
#define SWZ(o) ((o) ^ (((o) >> 3) & 0x70))

// ============================================================================
// Stage 1a: build A. K layout: [0,512) silu(x_i); [512 + i*8 + c) = basis_c(x_i).
// Per element: 4 nonzero basis values at slots t..t+3 of its 8-slot group ->
// pack [b0,b1,b2,b3] into 64 bits and shift into a 128-bit word (one uint4 store).
// Uniform cubic B-spline closed form (h = 0.4, knots -3.2..1.2).
// ============================================================================
#define GA_THREADS 256
#define GA_IPT 8
__global__ __launch_bounds__(GA_THREADS) void gen_A_kernel(const float* __restrict__ x) {
    int t = blockIdx.x * GA_THREADS + threadIdx.x;
    int row = t >> 6;                        // 64 threads per row (512/8)
    int i0 = (t & 63) * GA_IPT;
    const float* xp = x + (size_t)row * D_SZ + i0;
    float4 xa = *reinterpret_cast<const float4*>(xp);
    float4 xb = *reinterpret_cast<const float4*>(xp + 4);
    float xv[GA_IPT] = {xa.x, xa.y, xa.z, xa.w, xb.x, xb.y, xb.z, xb.w};

    __half* Arow = g_A + (size_t)row * KTOT;
    __half hs[GA_IPT];
#pragma unroll
    for (int e = 0; e < GA_IPT; ++e) {
        float v = xv[e];
        hs[e] = __float2half(__fdividef(v, 1.0f + __expf(-v)));   // silu

        float xc = fminf(fmaxf(v, -2.0f), 2.0f);
        float tp = (xc + 2.0f) * 2.5f;       // [0, 10]
        bool valid = tp < 8.0f;
        int tt = min((int)tp, 7);
        float u = tp - (float)tt;
        float um = 1.0f - u;
        float u2 = u * u, u3 = u2 * u;
        float b0 = um * um * um * (1.0f / 6.0f);
        float b1 = (3.0f * u3 - 6.0f * u2 + 4.0f) * (1.0f / 6.0f);
        float b2 = (-3.0f * u3 + 3.0f * u2 + 3.0f * u + 1.0f) * (1.0f / 6.0f);
        float b3 = u3 * (1.0f / 6.0f);

        __half2 p01 = __floats2half2_rn(b0, b1);   // b0 in low half
        __half2 p23 = __floats2half2_rn(b2, b3);
        uint64_t v64 = (uint64_t)reinterpret_cast<uint32_t&>(p01) |
                       ((uint64_t)reinterpret_cast<uint32_t&>(p23) << 32);
        int s = tt * 16;                     // bit offset in 128-bit group
        uint64_t lo, hi;
        if (s < 64) {
            lo = v64 << s;
            hi = s ? (v64 >> (64 - s)) : 0ull;
        } else {
            lo = 0ull;
            hi = v64 << (s - 64);
        }
        if (!valid) { lo = 0ull; hi = 0ull; }
        uint4 w;
        w.x = (uint32_t)lo; w.y = (uint32_t)(lo >> 32);
        w.z = (uint32_t)hi; w.w = (uint32_t)(hi >> 32);
        *reinterpret_cast<uint4*>(Arow + 512 + (size_t)(i0 + e) * 8) = w;
    }
    *reinterpret_cast<uint4*>(Arow + i0) = *reinterpret_cast<const uint4*>(hs);
}

// ============================================================================
// Stage 1b: pack weights, SAME K layout: W[o,i]=base; W[o, 512+i*8+c]=spline[o,i,c]
// ============================================================================
__global__ void gen_W_kernel(const float* __restrict__ bw, const float* __restrict__ sw) {
    int o = blockIdx.x;
    int i = threadIdx.x;                      // 512 threads
    __half* Wrow = g_W + (size_t)o * KTOT;
    Wrow[i] = __float2half(bw[(size_t)o * D_SZ + i]);
    const float* sp = sw + ((size_t)o * D_SZ + i) * 8;
    __half h[8];
#pragma unroll
    for (int c = 0; c < 8; ++c) h[c] = __float2half(sp[c]);
    *reinterpret_cast<uint4*>(Wrow + 512 + (size_t)i * 8) =
        *reinterpret_cast<const uint4*>(h);
}

// ============================================================================
// Stage 2: HMMA GEMM: out[16384, 512] = A[M, K=4608] @ W[N, K]^T
//   CTA 128x128, BK=64, 3-stage cp.async, 4 warps (64x64 each), 2 CTAs/SM.
// ============================================================================
__device__ __forceinline__ void load_stage(uint32_t sb, int s, int kt,
                                           int mbase, int nbase, int tid) {
    uint32_t stage = sb + s * STAGE_BYTES;
    const __half* agp = g_A + (size_t)mbase * KTOT + (size_t)kt * BK;
#pragma unroll
    for (int it = 0; it < (BM * 8) / NTHREADS; ++it) {   // 8 chunks / thread
        int c = tid + it * NTHREADS;
        int row = c >> 3, col = c & 7;
        uint32_t off = (uint32_t)(row * 128 + col * 16);
        cp_async16(stage + SWZ(off), agp + (size_t)row * KTOT + col * 8);
    }
    const __half* bgp = g_W + (size_t)nbase * KTOT + (size_t)kt * BK;
    uint32_t bbase = stage + SA_STAGE;
#pragma unroll
    for (int it = 0; it < (BN * 8) / NTHREADS; ++it) {   // 8 chunks / thread
        int c = tid + it * NTHREADS;
        int row = c >> 3, col = c & 7;
        uint32_t off = (uint32_t)(row * 128 + col * 16);
        cp_async16(bbase + SWZ(off), bgp + (size_t)row * KTOT + col * 8);
    }
}

__global__ __launch_bounds__(NTHREADS, 2) void kan_gemm_kernel(float* __restrict__ out) {
    extern __shared__ __align__(1024) char smem[];
    uint32_t sb = smem_u32(smem);
    int tid = threadIdx.x, wid = tid >> 5, lane = tid & 31;
    int mbase = blockIdx.y * BM, nbase = blockIdx.x * BN;
    int warp_m = wid & 1;            // 2 warp-rows of 64
    int warp_n = wid >> 1;           // 2 warp-cols of 64

    float acc[4][8][4];
#pragma unroll
    for (int i = 0; i < 4; ++i)
#pragma unroll
        for (int j = 0; j < 8; ++j)
#pragma unroll
            for (int q = 0; q < 4; ++q) acc[i][j][q] = 0.0f;

    // ldmatrix lane address components (within a stage)
    int a_row_in_tile = (lane & 7) + ((lane >> 3) & 1) * 8;
    int a_byte = (lane >> 4) * 16;
    int b_row_in_pair = (lane & 7) + (lane >> 4) * 8;
    int b_byte = ((lane >> 3) & 1) * 16;

    // prologue: fill stages 0..STAGES-2
#pragma unroll
    for (int p = 0; p < STAGES - 1; ++p) { load_stage(sb, p, p, mbase, nbase, tid); cp_commit(); }

    for (int kt = 0; kt < NKIT; ++kt) {
        int s = kt % STAGES;
        cp_wait<STAGES - 2>();            // group kt complete
        __syncthreads();                  // data visible + stage (kt-1) fully consumed
        int kload = kt + STAGES - 1;
        if (kload < NKIT) load_stage(sb, kload % STAGES, kload, mbase, nbase, tid);
        cp_commit();                      // commit every iter for uniform group accounting

        uint32_t astage = sb + s * STAGE_BYTES;
        uint32_t bstage = astage + SA_STAGE;
#pragma unroll
        for (int ks = 0; ks < BK / 16; ++ks) {
            int kbyte = ks * 32;
            uint32_t a[4][4];
#pragma unroll
            for (int mt = 0; mt < 4; ++mt) {
                int row = warp_m * 64 + mt * 16 + a_row_in_tile;
                uint32_t off = (uint32_t)(row * 128 + kbyte + a_byte);
                ldsm_x4(a[mt][0], a[mt][1], a[mt][2], a[mt][3], astage + SWZ(off));
            }
            uint32_t b[8][2];
#pragma unroll
            for (int pr = 0; pr < 4; ++pr) {
                int row = warp_n * 64 + pr * 16 + b_row_in_pair;
                uint32_t off = (uint32_t)(row * 128 + kbyte + b_byte);
                uint32_t r0, r1, r2, r3;
                ldsm_x4(r0, r1, r2, r3, bstage + SWZ(off));
                b[pr * 2 + 0][0] = r0; b[pr * 2 + 0][1] = r1;
                b[pr * 2 + 1][0] = r2; b[pr * 2 + 1][1] = r3;
            }
#pragma unroll
            for (int mt = 0; mt < 4; ++mt)
#pragma unroll
                for (int nt = 0; nt < 8; ++nt)
                    mma16816(acc[mt][nt][0], acc[mt][nt][1], acc[mt][nt][2], acc[mt][nt][3],
                             a[mt][0], a[mt][1], a[mt][2], a[mt][3],
                             b[nt][0], b[nt][1]);
        }
    }

    // epilogue: direct fp32 stores (8B per lane per tile-row, quad-coalesced)
    int r0 = mbase + warp_m * 64 + (lane >> 2);
    int c0 = nbase + warp_n * 64 + (lane & 3) * 2;
#pragma unroll
    for (int mt = 0; mt < 4; ++mt) {
#pragma unroll
        for (int nt = 0; nt < 8; ++nt) {
            float* p = out + (size_t)(r0 + mt * 16) * O_SZ + c0 + nt * 8;
            *reinterpret_cast<float2*>(p) = make_float2(acc[mt][nt][0], acc[mt][nt][1]);
            float* p2 = p + 8 * O_SZ;
            *reinterpret_cast<float2*>(p2) = make_float2(acc[mt][nt][2], acc[mt][nt][3]);
        }
    }
}

// ============================================================================
extern "C" void kernel_launch(void* const* d_in, const int* in_sizes, int n_in,
                              void* d_out, int out_size) {
    const float* x  = (const float*)d_in[0];
    const float* bw = (const float*)d_in[1];
    const float* sw = (const float*)d_in[2];
    float* out = (float*)d_out;

    cudaFuncSetAttribute(kan_gemm_kernel,
                         cudaFuncAttributeMaxDynamicSharedMemorySize, SMEM_BYTES);

    gen_A_kernel<<<(B_SZ * (D_SZ / GA_IPT)) / GA_THREADS, GA_THREADS>>>(x);
    gen_W_kernel<<<O_SZ, D_SZ>>>(bw, sw);

    // x-major grid: the 4 N-tiles of one M-tile run concurrently -> A reused in L2
    dim3 grid(O_SZ / BN, B_SZ / BM);   // (4, 128)
    kan_gemm_kernel<<<grid, NTHREADS, SMEM_BYTES>>>(out);
}

// round 10
// speedup vs baseline: 1.1930x; 1.1930x over previous
#include <cuda_runtime.h>
#include <cuda_fp16.h>
#include <cstdint>

// ---------------- problem dims ----------------
#define B_SZ 16384
#define D_SZ 512
#define O_SZ 512
#define KTOT 4608               // 512 silu + 4096 basis (i-major groups of 8)

// ---------------- GEMM tiling ----------------
#define BM 128
#define BN 128
#define BK 64                   // 64 fp16 = 128 bytes = one swizzled row
#define STAGES 3
#define NKIT (KTOT / BK)        // 72
#define NTHREADS 128            // 4 warps, warp tile 64x64

#define SA_STAGE (BM * BK * 2)              // 16 KB
#define SB_STAGE (BN * BK * 2)              // 16 KB
#define STAGE_BYTES (SA_STAGE + SB_STAGE)
#define SMEM_BYTES (STAGES * STAGE_BYTES)   // 96 KB  (x2 CTAs = 192 KB/SM)

// ---------------- scratch (device globals; no allocation allowed) ----------------
__device__ __half g_A[(size_t)B_SZ * KTOT];   // ~151 MB
__device__ __half g_W[(size_t)O_SZ * KTOT];   // ~4.7 MB

// ---------------- helpers ----------------
__device__ __forceinline__ uint32_t smem_u32(const void* p) {
    return (uint32_t)__cvta_generic_to_shared(p);
}
__device__ __forceinline__ void cp_async16(uint32_t saddr, const void* g) {
    asm volatile("cp.async.cg.shared.global [%0], [%1], 16;" :: "r"(saddr), "l"(g) : "memory");
}
__device__ __forceinline__ void cp_commit() {
    asm volatile("cp.async.commit_group;" ::: "memory");
}
template <int N> __device__ __forceinline__ void cp_wait() {
    asm volatile("cp.async.wait_group %0;" :: "n"(N) : "memory");
}
__device__ __forceinline__ void ldsm_x4(uint32_t& r0, uint32_t& r1, uint32_t& r2, uint32_t& r3,
                                        uint32_t addr) {
    asm volatile("ldmatrix.sync.aligned.m8n8.x4.shared.b16 {%0,%1,%2,%3}, [%4];"
                 : "=r"(r0), "=r"(r1), "=r"(r2), "=r"(r3) : "r"(addr));
}
__device__ __forceinline__ void mma16816(float& c0, float& c1, float& c2, float& c3,
                                         uint32_t a0, uint32_t a1, uint32_t a2, uint32_t a3,
                                         uint32_t b0, uint32_t b1) {
    asm volatile(
        "mma.sync.aligned.m16n8k16.row.col.f32.f16.f16.f32 "
        "{%0,%1,%2,%3}, {%4,%5,%6,%7}, {%8,%9}, {%0,%1,%2,%3};"
        : "+f"(c0), "+f"(c1), "+f"(c2), "+f"(c3)
        : "r"(a0), "r"(a1), "r"(a2), "r"(a3), "r"(b0), "r"(b1));
}
#define SWZ(o) ((o) ^ (((o) >> 3) & 0x70))

// ============================================================================
// Stage 1a: build A. K layout: [0,512) silu(x_i); [512 + i*8 + c) = basis_c(x_i).
// 64 threads per row; thread j handles i = j + 64*e (e = 0..7) so that per
// iteration: x loads coalesced, silu 2B stores contiguous (128B/rowgroup),
// basis 16B stores contiguous (1KB/rowgroup). Basis placement via one 128-bit
// funnel shift of the packed 4 nonzeros (slots t..t+3).
// ============================================================================
#define GA_THREADS 256
#define GA_ROWS_PER_BLK (GA_THREADS / 64)
__global__ __launch_bounds__(GA_THREADS) void gen_A_kernel(const float* __restrict__ x) {
    int j = threadIdx.x & 63;
    int row = blockIdx.x * GA_ROWS_PER_BLK + (threadIdx.x >> 6);
    const float* xrow = x + (size_t)row * D_SZ;
    __half* Arow = g_A + (size_t)row * KTOT;

#pragma unroll
    for (int e = 0; e < 8; ++e) {
        int i = j + 64 * e;
        float v = xrow[i];
        // silu (fast path; error ~1e-7, invisible under fp16 rounding)
        Arow[i] = __float2half(__fdividef(v, 1.0f + __expf(-v)));

        float xc = fminf(fmaxf(v, -2.0f), 2.0f);
        float tp = (xc + 2.0f) * 2.5f;       // [0, 10]
        bool valid = tp < 8.0f;
        int tt = min((int)tp, 7);
        float u = tp - (float)tt;
        float um = 1.0f - u;
        float u2 = u * u, u3 = u2 * u;
        float b0 = um * um * um * (1.0f / 6.0f);
        float b1 = (3.0f * u3 - 6.0f * u2 + 4.0f) * (1.0f / 6.0f);
        float b2 = (-3.0f * u3 + 3.0f * u2 + 3.0f * u + 1.0f) * (1.0f / 6.0f);
        float b3 = u3 * (1.0f / 6.0f);

        __half2 p01 = __floats2half2_rn(b0, b1);
        __half2 p23 = __floats2half2_rn(b2, b3);
        uint64_t v64 = (uint64_t)reinterpret_cast<uint32_t&>(p01) |
                       ((uint64_t)reinterpret_cast<uint32_t&>(p23) << 32);
        int s = tt * 16;                     // bit offset in 128-bit group
        uint64_t lo, hi;
        if (s < 64) {
            lo = v64 << s;
            hi = s ? (v64 >> (64 - s)) : 0ull;
        } else {
            lo = 0ull;
            hi = v64 << (s - 64);
        }
        if (!valid) { lo = 0ull; hi = 0ull; }
        uint4 w;
        w.x = (uint32_t)lo; w.y = (uint32_t)(lo >> 32);
        w.z = (uint32_t)hi; w.w = (uint32_t)(hi >> 32);
        *reinterpret_cast<uint4*>(Arow + 512 + (size_t)i * 8) = w;
    }
}

// ============================================================================
// Stage 1b: pack weights, SAME K layout: W[o,i]=base; W[o, 512+i*8+c]=spline[o,i,c]
// ============================================================================
__global__ void gen_W_kernel(const float* __restrict__ bw, const float* __restrict__ sw) {
    int o = blockIdx.x;
    int i = threadIdx.x;                      // 512 threads
    __half* Wrow = g_W + (size_t)o * KTOT;
    Wrow[i] = __float2half(bw[(size_t)o * D_SZ + i]);
    const float* sp = sw + ((size_t)o * D_SZ + i) * 8;
    __half h[8];
#pragma unroll
    for (int c = 0; c < 8; ++c) h[c] = __float2half(sp[c]);
    *reinterpret_cast<uint4*>(Wrow + 512 + (size_t)i * 8) =
        *reinterpret_cast<const uint4*>(h);
}

// ============================================================================
// Stage 2: HMMA GEMM: out[16384, 512] = A[M, K=4608] @ W[N, K]^T
//   CTA 128x128, BK=64, 3-stage cp.async, 4 warps (64x64 each), 2 CTAs/SM.
// ============================================================================
__device__ __forceinline__ void load_stage(uint32_t sb, int s, int kt,
                                           int mbase, int nbase, int tid) {
    uint32_t stage = sb + s * STAGE_BYTES;
    const __half* agp = g_A + (size_t)mbase * KTOT + (size_t)kt * BK;
#pragma unroll
    for (int it = 0; it < (BM * 8) / NTHREADS; ++it) {   // 8 chunks / thread
        int c = tid + it * NTHREADS;
        int row = c >> 3, col = c & 7;
        uint32_t off = (uint32_t)(row * 128 + col * 16);
        cp_async16(stage + SWZ(off), agp + (size_t)row * KTOT + col * 8);
    }
    const __half* bgp = g_W + (size_t)nbase * KTOT + (size_t)kt * BK;
    uint32_t bbase = stage + SA_STAGE;
#pragma unroll
    for (int it = 0; it < (BN * 8) / NTHREADS; ++it) {   // 8 chunks / thread
        int c = tid + it * NTHREADS;
        int row = c >> 3, col = c & 7;
        uint32_t off = (uint32_t)(row * 128 + col * 16);
        cp_async16(bbase + SWZ(off), bgp + (size_t)row * KTOT + col * 8);
    }
}

__global__ __launch_bounds__(NTHREADS, 2) void kan_gemm_kernel(float* __restrict__ out) {
    extern __shared__ __align__(1024) char smem[];
    uint32_t sb = smem_u32(smem);
    int tid = threadIdx.x, wid = tid >> 5, lane = tid & 31;
    int mbase = blockIdx.y * BM, nbase = blockIdx.x * BN;
    int warp_m = wid & 1;            // 2 warp-rows of 64
    int warp_n = wid >> 1;           // 2 warp-cols of 64

    float acc[4][8][4];
#pragma unroll
    for (int i = 0; i < 4; ++i)
#pragma unroll
        for (int j = 0; j < 8; ++j)
#pragma unroll
            for (int q = 0; q < 4; ++q) acc[i][j][q] = 0.0f;

    // ldmatrix lane address components (within a stage)
    int a_row_in_tile = (lane & 7) + ((lane >> 3) & 1) * 8;
    int a_byte = (lane >> 4) * 16;
    int b_row_in_pair = (lane & 7) + (lane >> 4) * 8;
    int b_byte = ((lane >> 3) & 1) * 16;

    // prologue: fill stages 0..STAGES-2
#pragma unroll
    for (int p = 0; p < STAGES - 1; ++p) { load_stage(sb, p, p, mbase, nbase, tid); cp_commit(); }

    for (int kt = 0; kt < NKIT; ++kt) {
        int s = kt % STAGES;
        cp_wait<STAGES - 2>();            // group kt complete
        __syncthreads();                  // data visible + stage (kt-1) fully consumed
        int kload = kt + STAGES - 1;
        if (kload < NKIT) load_stage(sb, kload % STAGES, kload, mbase, nbase, tid);
        cp_commit();                      // commit every iter for uniform group accounting

        uint32_t astage = sb + s * STAGE_BYTES;
        uint32_t bstage = astage + SA_STAGE;
#pragma unroll
        for (int ks = 0; ks < BK / 16; ++ks) {
            int kbyte = ks * 32;
            uint32_t a[4][4];
#pragma unroll
            for (int mt = 0; mt < 4; ++mt) {
                int row = warp_m * 64 + mt * 16 + a_row_in_tile;
                uint32_t off = (uint32_t)(row * 128 + kbyte + a_byte);
                ldsm_x4(a[mt][0], a[mt][1], a[mt][2], a[mt][3], astage + SWZ(off));
            }
            uint32_t b[8][2];
#pragma unroll
            for (int pr = 0; pr < 4; ++pr) {
                int row = warp_n * 64 + pr * 16 + b_row_in_pair;
                uint32_t off = (uint32_t)(row * 128 + kbyte + b_byte);
                uint32_t r0, r1, r2, r3;
                ldsm_x4(r0, r1, r2, r3, bstage + SWZ(off));
                b[pr * 2 + 0][0] = r0; b[pr * 2 + 0][1] = r1;
                b[pr * 2 + 1][0] = r2; b[pr * 2 + 1][1] = r3;
            }
#pragma unroll
            for (int mt = 0; mt < 4; ++mt)
#pragma unroll
                for (int nt = 0; nt < 8; ++nt)
                    mma16816(acc[mt][nt][0], acc[mt][nt][1], acc[mt][nt][2], acc[mt][nt][3],
                             a[mt][0], a[mt][1], a[mt][2], a[mt][3],
                             b[nt][0], b[nt][1]);
        }
    }

    // epilogue: direct fp32 stores (8B per lane per tile-row, quad-coalesced)
    int r0 = mbase + warp_m * 64 + (lane >> 2);
    int c0 = nbase + warp_n * 64 + (lane & 3) * 2;
#pragma unroll
    for (int mt = 0; mt < 4; ++mt) {
#pragma unroll
        for (int nt = 0; nt < 8; ++nt) {
            float* p = out + (size_t)(r0 + mt * 16) * O_SZ + c0 + nt * 8;
            *reinterpret_cast<float2*>(p) = make_float2(acc[mt][nt][0], acc[mt][nt][1]);
            float* p2 = p + 8 * O_SZ;
            *reinterpret_cast<float2*>(p2) = make_float2(acc[mt][nt][2], acc[mt][nt][3]);
        }
    }
}

// ============================================================================
extern "C" void kernel_launch(void* const* d_in, const int* in_sizes, int n_in,
                              void* d_out, int out_size) {
    const float* x  = (const float*)d_in[0];
    const float* bw = (const float*)d_in[1];
    const float* sw = (const float*)d_in[2];
    float* out = (float*)d_out;

    cudaFuncSetAttribute(kan_gemm_kernel,
                         cudaFuncAttributeMaxDynamicSharedMemorySize, SMEM_BYTES);

    gen_A_kernel<<<B_SZ / GA_ROWS_PER_BLK, GA_THREADS>>>(x);
    gen_W_kernel<<<O_SZ, D_SZ>>>(bw, sw);

    // x-major grid: the 4 N-tiles of one M-tile run concurrently -> A reused in L2
    dim3 grid(O_SZ / BN, B_SZ / BM);   // (4, 128)
    kan_gemm_kernel<<<grid, NTHREADS, SMEM_BYTES>>>(out);
}

// round 11
// speedup vs baseline: 1.1957x; 1.0022x over previous
#include <cuda_runtime.h>
#include <cuda_fp16.h>
#include <cstdint>

// ---------------- problem dims ----------------
#define B_SZ 16384
#define D_SZ 512
#define O_SZ 512
#define KTOT 4608               // 512 silu + 4096 basis (i-major groups of 8)

// ---------------- GEMM tiling ----------------
#define BM 128
#define BN 128
#define BK 64                   // 64 fp16 = 128 bytes = one swizzled row
#define STAGES 3
#define NKIT (KTOT / BK)        // 72
#define NTHREADS 128            // 4 warps, warp tile 64x64

#define SA_STAGE (BM * BK * 2)              // 16 KB
#define SB_STAGE (BN * BK * 2)              // 16 KB
#define STAGE_BYTES (SA_STAGE + SB_STAGE)
#define SMEM_BYTES (STAGES * STAGE_BYTES)   // 96 KB  (x2 CTAs = 192 KB/SM)

// ---------------- scratch (device globals; no allocation allowed) ----------------
__device__ __half g_A[(size_t)B_SZ * KTOT];   // ~151 MB
__device__ __half g_W[(size_t)O_SZ * KTOT];   // ~4.7 MB

// ---------------- helpers ----------------
__device__ __forceinline__ uint32_t smem_u32(const void* p) {
    return (uint32_t)__cvta_generic_to_shared(p);
}
__device__ __forceinline__ void cp_async16(uint32_t saddr, const void* g) {
    asm volatile("cp.async.cg.shared.global [%0], [%1], 16;" :: "r"(saddr), "l"(g) : "memory");
}
__device__ __forceinline__ void cp_commit() {
    asm volatile("cp.async.commit_group;" ::: "memory");
}
template <int N> __device__ __forceinline__ void cp_wait() {
    asm volatile("cp.async.wait_group %0;" :: "n"(N) : "memory");
}
__device__ __forceinline__ void ldsm_x4(uint32_t& r0, uint32_t& r1, uint32_t& r2, uint32_t& r3,
                                        uint32_t addr) {
    asm volatile("ldmatrix.sync.aligned.m8n8.x4.shared.b16 {%0,%1,%2,%3}, [%4];"
                 : "=r"(r0), "=r"(r1), "=r"(r2), "=r"(r3) : "r"(addr));
}
__device__ __forceinline__ void mma16816(float& c0, float& c1, float& c2, float& c3,
                                         uint32_t a0, uint32_t a1, uint32_t a2, uint32_t a3,
                                         uint32_t b0, uint32_t b1) {
    asm volatile(
        "mma.sync.aligned.m16n8k16.row.col.f32.f16.f16.f32 "
        "{%0,%1,%2,%3}, {%4,%5,%6,%7}, {%8,%9}, {%0,%1,%2,%3};"
        : "+f"(c0), "+f"(c1), "+f"(c2), "+f"(c3)
        : "r"(a0), "r"(a1), "r"(a2), "r"(a3), "r"(b0), "r"(b1));
}
#define SWZ(o) ((o) ^ (((o) >> 3) & 0x70))

// ============================================================================
// Stage 1a: build A. K layout: [0,512) silu(x_i); [512 + i*8 + c) = basis_c(x_i).
// 64 threads per row; thread j handles i = j + 64*e (e = 0..7) so that per
// iteration: x loads coalesced, silu 2B stores contiguous (128B/rowgroup),
// basis 16B stores contiguous (1KB/rowgroup). Basis placement via one 128-bit
// funnel shift of the packed 4 nonzeros (slots t..t+3).
// ============================================================================
#define GA_THREADS 256
#define GA_ROWS_PER_BLK (GA_THREADS / 64)
__global__ __launch_bounds__(GA_THREADS) void gen_A_kernel(const float* __restrict__ x) {
    int j = threadIdx.x & 63;
    int row = blockIdx.x * GA_ROWS_PER_BLK + (threadIdx.x >> 6);
    const float* xrow = x + (size_t)row * D_SZ;
    __half* Arow = g_A + (size_t)row * KTOT;

#pragma unroll
    for (int e = 0; e < 8; ++e) {
        int i = j + 64 * e;
        float v = xrow[i];
        // silu (fast path; error ~1e-7, invisible under fp16 rounding)
        Arow[i] = __float2half(__fdividef(v, 1.0f + __expf(-v)));

        float xc = fminf(fmaxf(v, -2.0f), 2.0f);
        float tp = (xc + 2.0f) * 2.5f;       // [0, 10]
        bool valid = tp < 8.0f;
        int tt = min((int)tp, 7);
        float u = tp - (float)tt;
        float um = 1.0f - u;
        float u2 = u * u, u3 = u2 * u;
        float b0 = um * um * um * (1.0f / 6.0f);
        float b1 = (3.0f * u3 - 6.0f * u2 + 4.0f) * (1.0f / 6.0f);
        float b2 = (-3.0f * u3 + 3.0f * u2 + 3.0f * u + 1.0f) * (1.0f / 6.0f);
        float b3 = u3 * (1.0f / 6.0f);

        __half2 p01 = __floats2half2_rn(b0, b1);
        __half2 p23 = __floats2half2_rn(b2, b3);
        uint64_t v64 = (uint64_t)reinterpret_cast<uint32_t&>(p01) |
                       ((uint64_t)reinterpret_cast<uint32_t&>(p23) << 32);
        int s = tt * 16;                     // bit offset in 128-bit group
        uint64_t lo, hi;
        if (s < 64) {
            lo = v64 << s;
            hi = s ? (v64 >> (64 - s)) : 0ull;
        } else {
            lo = 0ull;
            hi = v64 << (s - 64);
        }
        if (!valid) { lo = 0ull; hi = 0ull; }
        uint4 w;
        w.x = (uint32_t)lo; w.y = (uint32_t)(lo >> 32);
        w.z = (uint32_t)hi; w.w = (uint32_t)(hi >> 32);
        *reinterpret_cast<uint4*>(Arow + 512 + (size_t)i * 8) = w;
    }
}

// ============================================================================
// Stage 1b: pack weights, SAME K layout: W[o,i]=base; W[o, 512+i*8+c]=spline[o,i,c]
// ============================================================================
__global__ void gen_W_kernel(const float* __restrict__ bw, const float* __restrict__ sw) {
    int o = blockIdx.x;
    int i = threadIdx.x;                      // 512 threads
    __half* Wrow = g_W + (size_t)o * KTOT;
    Wrow[i] = __float2half(bw[(size_t)o * D_SZ + i]);
    const float* sp = sw + ((size_t)o * D_SZ + i) * 8;
    __half h[8];
#pragma unroll
    for (int c = 0; c < 8; ++c) h[c] = __float2half(sp[c]);
    *reinterpret_cast<uint4*>(Wrow + 512 + (size_t)i * 8) =
        *reinterpret_cast<const uint4*>(h);
}

// ============================================================================
// Stage 2: HMMA GEMM: out[16384, 512] = A[M, K=4608] @ W[N, K]^T
//   CTA 128x128, BK=64, 3-stage cp.async, 4 warps (64x64 each), 2 CTAs/SM.
// ============================================================================
__device__ __forceinline__ void load_stage(uint32_t sb, int s, int kt,
                                           int mbase, int nbase, int tid) {
    uint32_t stage = sb + s * STAGE_BYTES;
    const __half* agp = g_A + (size_t)mbase * KTOT + (size_t)kt * BK;
#pragma unroll
    for (int it = 0; it < (BM * 8) / NTHREADS; ++it) {   // 8 chunks / thread
        int c = tid + it * NTHREADS;
        int row = c >> 3, col = c & 7;
        uint32_t off = (uint32_t)(row * 128 + col * 16);
        cp_async16(stage + SWZ(off), agp + (size_t)row * KTOT + col * 8);
    }
    const __half* bgp = g_W + (size_t)nbase * KTOT + (size_t)kt * BK;
    uint32_t bbase = stage + SA_STAGE;
#pragma unroll
    for (int it = 0; it < (BN * 8) / NTHREADS; ++it) {   // 8 chunks / thread
        int c = tid + it * NTHREADS;
        int row = c >> 3, col = c & 7;
        uint32_t off = (uint32_t)(row * 128 + col * 16);
        cp_async16(bbase + SWZ(off), bgp + (size_t)row * KTOT + col * 8);
    }
}

__global__ __launch_bounds__(NTHREADS, 2) void kan_gemm_kernel(float* __restrict__ out) {
    extern __shared__ __align__(1024) char smem[];
    uint32_t sb = smem_u32(smem);
    int tid = threadIdx.x, wid = tid >> 5, lane = tid & 31;
    int mbase = blockIdx.y * BM, nbase = blockIdx.x * BN;
    int warp_m = wid & 1;            // 2 warp-rows of 64
    int warp_n = wid >> 1;           // 2 warp-cols of 64

    float acc[4][8][4];
#pragma unroll
    for (int i = 0; i < 4; ++i)
#pragma unroll
        for (int j = 0; j < 8; ++j)
#pragma unroll
            for (int q = 0; q < 4; ++q) acc[i][j][q] = 0.0f;

    // ldmatrix lane address components (within a stage)
    int a_row_in_tile = (lane & 7) + ((lane >> 3) & 1) * 8;
    int a_byte = (lane >> 4) * 16;
    int b_row_in_pair = (lane & 7) + (lane >> 4) * 8;
    int b_byte = ((lane >> 3) & 1) * 16;

    // prologue: fill stages 0..STAGES-2
#pragma unroll
    for (int p = 0; p < STAGES - 1; ++p) { load_stage(sb, p, p, mbase, nbase, tid); cp_commit(); }

    for (int kt = 0; kt < NKIT; ++kt) {
        int s = kt % STAGES;
        cp_wait<STAGES - 2>();            // group kt complete
        __syncthreads();                  // data visible + stage (kt-1) fully consumed
        int kload = kt + STAGES - 1;
        if (kload < NKIT) load_stage(sb, kload % STAGES, kload, mbase, nbase, tid);
        cp_commit();                      // commit every iter for uniform group accounting

        uint32_t astage = sb + s * STAGE_BYTES;
        uint32_t bstage = astage + SA_STAGE;
#pragma unroll
        for (int ks = 0; ks < BK / 16; ++ks) {
            int kbyte = ks * 32;
            uint32_t a[4][4];
#pragma unroll
            for (int mt = 0; mt < 4; ++mt) {
                int row = warp_m * 64 + mt * 16 + a_row_in_tile;
                uint32_t off = (uint32_t)(row * 128 + kbyte + a_byte);
                ldsm_x4(a[mt][0], a[mt][1], a[mt][2], a[mt][3], astage + SWZ(off));
            }
            uint32_t b[8][2];
#pragma unroll
            for (int pr = 0; pr < 4; ++pr) {
                int row = warp_n * 64 + pr * 16 + b_row_in_pair;
                uint32_t off = (uint32_t)(row * 128 + kbyte + b_byte);
                uint32_t r0, r1, r2, r3;
                ldsm_x4(r0, r1, r2, r3, bstage + SWZ(off));
                b[pr * 2 + 0][0] = r0; b[pr * 2 + 0][1] = r1;
                b[pr * 2 + 1][0] = r2; b[pr * 2 + 1][1] = r3;
            }
#pragma unroll
            for (int mt = 0; mt < 4; ++mt)
#pragma unroll
                for (int nt = 0; nt < 8; ++nt)
                    mma16816(acc[mt][nt][0], acc[mt][nt][1], acc[mt][nt][2], acc[mt][nt][3],
                             a[mt][0], a[mt][1], a[mt][2], a[mt][3],
                             b[nt][0], b[nt][1]);
        }
    }

    // epilogue: direct fp32 stores (8B per lane per tile-row, quad-coalesced)
    int r0 = mbase + warp_m * 64 + (lane >> 2);
    int c0 = nbase + warp_n * 64 + (lane & 3) * 2;
#pragma unroll
    for (int mt = 0; mt < 4; ++mt) {
#pragma unroll
        for (int nt = 0; nt < 8; ++nt) {
            float* p = out + (size_t)(r0 + mt * 16) * O_SZ + c0 + nt * 8;
            *reinterpret_cast<float2*>(p) = make_float2(acc[mt][nt][0], acc[mt][nt][1]);
            float* p2 = p + 8 * O_SZ;
            *reinterpret_cast<float2*>(p2) = make_float2(acc[mt][nt][2], acc[mt][nt][3]);
        }
    }
}

// ============================================================================
extern "C" void kernel_launch(void* const* d_in, const int* in_sizes, int n_in,
                              void* d_out, int out_size) {
    const float* x  = (const float*)d_in[0];
    const float* bw = (const float*)d_in[1];
    const float* sw = (const float*)d_in[2];
    float* out = (float*)d_out;

    cudaFuncSetAttribute(kan_gemm_kernel,
                         cudaFuncAttributeMaxDynamicSharedMemorySize, SMEM_BYTES);

    gen_A_kernel<<<B_SZ / GA_ROWS_PER_BLK, GA_THREADS>>>(x);
    gen_W_kernel<<<O_SZ, D_SZ>>>(bw, sw);

    // x-major grid: the 4 N-tiles of one M-tile run concurrently -> A reused in L2
    dim3 grid(O_SZ / BN, B_SZ / BM);   // (4, 128)
    kan_gemm_kernel<<<grid, NTHREADS, SMEM_BYTES>>>(out);
}